// round 1
// baseline (speedup 1.0000x reference)
#include <cuda_runtime.h>
#include <stdint.h>
#include <math.h>

// ---------------------------------------------------------------------------
// Permutation indices: reproduce jax.random.permutation(jax.random.key(42), 1024)[:256]
// JAX threefry2x32, partitionable mode (default since JAX 0.4.36):
//   key(42) = (0, 42)
//   split: counts lane i = (0, i); subkey = (out0(lane1), out1(lane1))
//   bits(1024): lane i = (0, i), bits[i] = out0 ^ out1
//   one round of stable ascending sort_key_val(bits, arange(1024))
// ---------------------------------------------------------------------------

__device__ int g_perm[256];

__device__ __forceinline__ uint32_t rotl32(uint32_t x, int r) {
    return (x << r) | (x >> (32 - r));
}

__device__ __forceinline__ void threefry2x32(uint32_t k0, uint32_t k1,
                                             uint32_t c0, uint32_t c1,
                                             uint32_t& o0, uint32_t& o1) {
    uint32_t ks2 = k0 ^ k1 ^ 0x1BD11BDAu;
    uint32_t x0 = c0 + k0;
    uint32_t x1 = c1 + k1;
#define TF_G(r0, r1, r2, r3)                          \
    x0 += x1; x1 = rotl32(x1, r0); x1 ^= x0;          \
    x0 += x1; x1 = rotl32(x1, r1); x1 ^= x0;          \
    x0 += x1; x1 = rotl32(x1, r2); x1 ^= x0;          \
    x0 += x1; x1 = rotl32(x1, r3); x1 ^= x0;
    TF_G(13, 15, 26, 6)   x0 += k1;  x1 += ks2 + 1u;
    TF_G(17, 29, 16, 24)  x0 += ks2; x1 += k0 + 2u;
    TF_G(13, 15, 26, 6)   x0 += k0;  x1 += k1 + 3u;
    TF_G(17, 29, 16, 24)  x0 += k1;  x1 += ks2 + 4u;
    TF_G(13, 15, 26, 6)   x0 += ks2; x1 += k0 + 5u;
#undef TF_G
    o0 = x0; o1 = x1;
}

__global__ void perm_kernel() {
    __shared__ unsigned long long keys[1024];
    const int t = threadIdx.x;  // 1024 threads

    // subkey = split(key(0,42))[1]  -> counts lane (0, 1)
    uint32_t sk0, sk1;
    threefry2x32(0u, 42u, 0u, 1u, sk0, sk1);

    // random bits, lane (0, t), 32-bit output = hi ^ lo
    uint32_t b0, b1;
    threefry2x32(sk0, sk1, 0u, (uint32_t)t, b0, b1);
    uint32_t bits = b0 ^ b1;

    // composite key: (bits << 32) | index -> strict '<' gives stable rank
    keys[t] = ((unsigned long long)bits << 32) | (unsigned long long)(uint32_t)t;
    __syncthreads();

    unsigned long long mine = keys[t];
    int rank = 0;
    for (int j = 0; j < 1024; j++) {
        rank += (keys[j] < mine) ? 1 : 0;
    }
    if (rank < 256) {
        g_perm[rank] = (int)(mine & 0xFFFFFFFFull);
    }
}

// ---------------------------------------------------------------------------
// Main LRF kernel: one block of 256 threads per batch row b.
//   xs = x0i - x0 (note: this is the reference's x AFTER its sign flip)
//   xxt = xs xs^T / 1024 (sign-invariant)
//   z = smallest eigenvector of xxt (fp64 analytic 3x3 solve)
//   s_ref = z . sum(x0 - x0i) = -z . sum(xs);  zp = sign(s_ref) * z
//   norm_c = zp . xs_c; vi = xs - norm*zp; alpha=(1-|xs|)^2; beta=norm^2
//   vi_c = sum_c alpha*beta*vi;  xp_ax = normalize(vi_c);  yp = xp_ax x zp
//   out[b, i, s] = row_i . xs[:, perm[s]]  (R_LRF = 1)
// ---------------------------------------------------------------------------

__global__ __launch_bounds__(256) void lrf_kernel(
    const float* __restrict__ x0,
    const float* __restrict__ x0i,
    float* __restrict__ out)
{
    const int b = blockIdx.x;
    const int t = threadIdx.x;
    const int w = t >> 5;
    const int lane = t & 31;

    __shared__ float sx0[1024];
    __shared__ float sx1[1024];
    __shared__ float sx2[1024];
    __shared__ float redf[8][9];
    __shared__ float sbc[9];  // [0:3) zp, [3:6) xp_ax, [6:9) yp

    const float px = __ldg(&x0[3 * b + 0]);
    const float py = __ldg(&x0[3 * b + 1]);
    const float pz = __ldg(&x0[3 * b + 2]);

    const float* base = x0i + (size_t)b * 3072;
    const int c0 = t * 4;

    float4 u0 = *reinterpret_cast<const float4*>(base + c0);
    float4 u1 = *reinterpret_cast<const float4*>(base + 1024 + c0);
    float4 u2 = *reinterpret_cast<const float4*>(base + 2048 + c0);

    float X[4] = {u0.x - px, u0.y - px, u0.z - px, u0.w - px};
    float Y[4] = {u1.x - py, u1.y - py, u1.z - py, u1.w - py};
    float Z[4] = {u2.x - pz, u2.y - pz, u2.z - pz, u2.w - pz};

    *reinterpret_cast<float4*>(&sx0[c0]) = make_float4(X[0], X[1], X[2], X[3]);
    *reinterpret_cast<float4*>(&sx1[c0]) = make_float4(Y[0], Y[1], Y[2], Y[3]);
    *reinterpret_cast<float4*>(&sx2[c0]) = make_float4(Z[0], Z[1], Z[2], Z[3]);

    // ----- phase 1: accumulate xxt (6) and column sum (3) -----
    float a00 = 0.f, a01 = 0.f, a02 = 0.f, a11 = 0.f, a12 = 0.f, a22 = 0.f;
    float s0 = 0.f, s1 = 0.f, s2 = 0.f;
#pragma unroll
    for (int k = 0; k < 4; k++) {
        float x = X[k], y = Y[k], z = Z[k];
        a00 = fmaf(x, x, a00); a01 = fmaf(x, y, a01); a02 = fmaf(x, z, a02);
        a11 = fmaf(y, y, a11); a12 = fmaf(y, z, a12); a22 = fmaf(z, z, a22);
        s0 += x; s1 += y; s2 += z;
    }
#pragma unroll
    for (int o = 16; o; o >>= 1) {
        a00 += __shfl_down_sync(0xffffffffu, a00, o);
        a01 += __shfl_down_sync(0xffffffffu, a01, o);
        a02 += __shfl_down_sync(0xffffffffu, a02, o);
        a11 += __shfl_down_sync(0xffffffffu, a11, o);
        a12 += __shfl_down_sync(0xffffffffu, a12, o);
        a22 += __shfl_down_sync(0xffffffffu, a22, o);
        s0  += __shfl_down_sync(0xffffffffu, s0, o);
        s1  += __shfl_down_sync(0xffffffffu, s1, o);
        s2  += __shfl_down_sync(0xffffffffu, s2, o);
    }
    if (lane == 0) {
        redf[w][0] = a00; redf[w][1] = a01; redf[w][2] = a02;
        redf[w][3] = a11; redf[w][4] = a12; redf[w][5] = a22;
        redf[w][6] = s0;  redf[w][7] = s1;  redf[w][8] = s2;
    }
    __syncthreads();

    // ----- phase 2: eigen solve + sign (thread 0, fp64) -----
    if (t == 0) {
        double A00 = 0, A01 = 0, A02 = 0, A11 = 0, A12 = 0, A22 = 0;
        double S0 = 0, S1 = 0, S2 = 0;
#pragma unroll
        for (int i = 0; i < 8; i++) {
            A00 += redf[i][0]; A01 += redf[i][1]; A02 += redf[i][2];
            A11 += redf[i][3]; A12 += redf[i][4]; A22 += redf[i][5];
            S0  += redf[i][6]; S1  += redf[i][7]; S2  += redf[i][8];
        }
        const double invC = 1.0 / 1024.0;
        A00 *= invC; A01 *= invC; A02 *= invC;
        A11 *= invC; A12 *= invC; A22 *= invC;

        // smallest eigenvalue (trigonometric method)
        double q = (A00 + A11 + A22) * (1.0 / 3.0);
        double b00 = A00 - q, b11 = A11 - q, b22 = A22 - q;
        double p2 = b00 * b00 + b11 * b11 + b22 * b22
                  + 2.0 * (A01 * A01 + A02 * A02 + A12 * A12);
        double p = sqrt(p2 * (1.0 / 6.0));
        double lmin;
        if (p < 1e-300) {
            lmin = q;
        } else {
            double ip = 1.0 / p;
            double c00 = b00 * ip, c11 = b11 * ip, c22 = b22 * ip;
            double c01 = A01 * ip, c02 = A02 * ip, c12 = A12 * ip;
            double det = c00 * (c11 * c22 - c12 * c12)
                       - c01 * (c01 * c22 - c12 * c02)
                       + c02 * (c01 * c12 - c11 * c02);
            double r = 0.5 * det;
            r = r > 1.0 ? 1.0 : (r < -1.0 ? -1.0 : r);
            double phi = acos(r) * (1.0 / 3.0);
            lmin = q + 2.0 * p * cos(phi + 2.0943951023931953);  // + 2*pi/3 -> smallest
        }

        // eigenvector via cross products of rows of (A - lmin I)
        double m00 = A00 - lmin, m11 = A11 - lmin, m22 = A22 - lmin;
        // r0 = (m00, A01, A02), r1 = (A01, m11, A12), r2 = (A02, A12, m22)
        double cx0 = A01 * A12 - A02 * m11;   // r0 x r1
        double cy0 = A02 * A01 - m00 * A12;
        double cz0 = m00 * m11 - A01 * A01;
        double cx1 = A01 * m22 - A02 * A12;   // r0 x r2
        double cy1 = A02 * A02 - m00 * m22;
        double cz1 = m00 * A12 - A01 * A02;
        double cx2 = m11 * m22 - A12 * A12;   // r1 x r2
        double cy2 = A12 * A02 - A01 * m22;
        double cz2 = A01 * A12 - m11 * A02;
        double n0 = cx0 * cx0 + cy0 * cy0 + cz0 * cz0;
        double n1 = cx1 * cx1 + cy1 * cy1 + cz1 * cz1;
        double n2 = cx2 * cx2 + cy2 * cy2 + cz2 * cz2;
        double zx, zy, zz, nn;
        if (n0 >= n1 && n0 >= n2)      { zx = cx0; zy = cy0; zz = cz0; nn = n0; }
        else if (n1 >= n2)             { zx = cx1; zy = cy1; zz = cz1; nn = n1; }
        else                           { zx = cx2; zy = cy2; zz = cz2; nn = n2; }
        if (nn < 1e-300) { zx = 0.0; zy = 0.0; zz = 1.0; nn = 1.0; }
        double inv = 1.0 / sqrt(nn);
        zx *= inv; zy *= inv; zz *= inv;

        // sign: s_ref = z . sum(xp - xpi) = -(z . sum(xs))
        double s = -(zx * S0 + zy * S1 + zz * S2);
        double sg = (s < 0.0) ? -1.0 : 1.0;
        sbc[0] = (float)(zx * sg);
        sbc[1] = (float)(zy * sg);
        sbc[2] = (float)(zz * sg);
    }
    __syncthreads();

    // ----- phase 3: vi_c accumulation (fp32, matches reference math) -----
    const float zpx = sbc[0], zpy = sbc[1], zpz = sbc[2];
    float v0 = 0.f, v1 = 0.f, v2 = 0.f;
#pragma unroll
    for (int k = 0; k < 4; k++) {
        float x = X[k], y = Y[k], z = Z[k];
        float nrm = fmaf(zpx, x, fmaf(zpy, y, zpz * z));
        float l2  = sqrtf(fmaf(x, x, fmaf(y, y, z * z)));
        float am  = 1.0f - l2;              // R_LRF = 1
        float coef = (am * am) * (nrm * nrm);
        v0 = fmaf(coef, fmaf(-nrm, zpx, x), v0);
        v1 = fmaf(coef, fmaf(-nrm, zpy, y), v1);
        v2 = fmaf(coef, fmaf(-nrm, zpz, z), v2);
    }
#pragma unroll
    for (int o = 16; o; o >>= 1) {
        v0 += __shfl_down_sync(0xffffffffu, v0, o);
        v1 += __shfl_down_sync(0xffffffffu, v1, o);
        v2 += __shfl_down_sync(0xffffffffu, v2, o);
    }
    if (lane == 0) {
        redf[w][0] = v0; redf[w][1] = v1; redf[w][2] = v2;
    }
    __syncthreads();

    if (t == 0) {
        float c0f = 0.f, c1f = 0.f, c2f = 0.f;
#pragma unroll
        for (int i = 0; i < 8; i++) {
            c0f += redf[i][0]; c1f += redf[i][1]; c2f += redf[i][2];
        }
        float nrm2 = fmaf(c0f, c0f, fmaf(c1f, c1f, c2f * c2f));
        float inv = 1.0f / sqrtf(nrm2);
        float ax = c0f * inv, ay = c1f * inv, az = c2f * inv;
        // yp = xp_ax x zp
        float yx = ay * sbc[2] - az * sbc[1];
        float yy = az * sbc[0] - ax * sbc[2];
        float yz = ax * sbc[1] - ay * sbc[0];
        sbc[3] = ax; sbc[4] = ay; sbc[5] = az;
        sbc[6] = yx; sbc[7] = yy; sbc[8] = yz;
    }
    __syncthreads();

    // ----- phase 4: project 256 sampled columns -----
    const float ax = sbc[3], ay = sbc[4], az = sbc[5];
    const float yx = sbc[6], yy = sbc[7], yz = sbc[8];
    const int ind = g_perm[t];
    const float vx = sx0[ind], vy = sx1[ind], vz = sx2[ind];
    const size_t ob = (size_t)b * 768 + t;
    out[ob]       = fmaf(ax, vx, fmaf(ay, vy, az * vz));
    out[ob + 256] = fmaf(yx, vx, fmaf(yy, vy, yz * vz));
    out[ob + 512] = fmaf(zpx, vx, fmaf(zpy, vy, zpz * vz));
}

// ---------------------------------------------------------------------------

extern "C" void kernel_launch(void* const* d_in, const int* in_sizes, int n_in,
                              void* d_out, int out_size) {
    const float* x0  = (const float*)d_in[0];
    const float* x0i = (const float*)d_in[1];
    // x0 is the smaller tensor (B*3 vs B*3*1024); guard against metadata order.
    if (n_in >= 2 && in_sizes[0] > in_sizes[1]) {
        const float* tmp = x0; x0 = x0i; x0i = tmp;
    }
    int B;
    if (in_sizes[0] <= in_sizes[1]) B = in_sizes[0] / 3;
    else                            B = in_sizes[1] / 3;

    float* out = (float*)d_out;

    perm_kernel<<<1, 1024>>>();
    lrf_kernel<<<B, 256>>>(x0, x0i, out);
}

// round 3
// speedup vs baseline: 3.7115x; 3.7115x over previous
#include <cuda_runtime.h>
#include <stdint.h>
#include <math.h>

// ---------------------------------------------------------------------------
// Permutation: reproduce jax.random.permutation(jax.random.key(42), 1024)[:256]
// threefry2x32 (partitionable): key(42)=(0,42); split lane (0,1) -> subkey;
// bits lane (0,i) -> out0^out1; one stable ascending sort round.
// Bitonic sort on composite (bits<<32 | idx) keys == stable sort by bits.
// Builds g_inv[col] = sample slot (0..255) or -1.
// ---------------------------------------------------------------------------

__device__ int g_inv[1024];

__device__ __forceinline__ uint32_t rotl32(uint32_t x, int r) {
    return (x << r) | (x >> (32 - r));
}

__device__ __forceinline__ void threefry2x32(uint32_t k0, uint32_t k1,
                                             uint32_t c0, uint32_t c1,
                                             uint32_t& o0, uint32_t& o1) {
    uint32_t ks2 = k0 ^ k1 ^ 0x1BD11BDAu;
    uint32_t x0 = c0 + k0;
    uint32_t x1 = c1 + k1;
#define TF_G(r0, r1, r2, r3)                          \
    x0 += x1; x1 = rotl32(x1, r0); x1 ^= x0;          \
    x0 += x1; x1 = rotl32(x1, r1); x1 ^= x0;          \
    x0 += x1; x1 = rotl32(x1, r2); x1 ^= x0;          \
    x0 += x1; x1 = rotl32(x1, r3); x1 ^= x0;
    TF_G(13, 15, 26, 6)   x0 += k1;  x1 += ks2 + 1u;
    TF_G(17, 29, 16, 24)  x0 += ks2; x1 += k0 + 2u;
    TF_G(13, 15, 26, 6)   x0 += k0;  x1 += k1 + 3u;
    TF_G(17, 29, 16, 24)  x0 += k1;  x1 += ks2 + 4u;
    TF_G(13, 15, 26, 6)   x0 += ks2; x1 += k0 + 5u;
#undef TF_G
    o0 = x0; o1 = x1;
}

__global__ void perm_kernel() {
    __shared__ unsigned long long keys[1024];
    const int t = threadIdx.x;  // 1024 threads

    uint32_t sk0, sk1;
    threefry2x32(0u, 42u, 0u, 1u, sk0, sk1);
    uint32_t b0, b1;
    threefry2x32(sk0, sk1, 0u, (uint32_t)t, b0, b1);
    uint32_t bits = b0 ^ b1;

    keys[t] = ((unsigned long long)bits << 32) | (unsigned long long)(uint32_t)t;
    __syncthreads();

    for (int k = 2; k <= 1024; k <<= 1) {
        for (int j = k >> 1; j > 0; j >>= 1) {
            int ixj = t ^ j;
            if (ixj > t) {
                unsigned long long a = keys[t];
                unsigned long long b = keys[ixj];
                bool asc = (t & k) == 0;
                if ((a > b) == asc) {
                    keys[t] = b;
                    keys[ixj] = a;
                }
            }
            __syncthreads();
        }
    }

    int col = (int)(keys[t] & 0xFFFFFFFFull);
    g_inv[col] = (t < 256) ? t : -1;
}

// ---------------------------------------------------------------------------
// Main LRF kernel: one block of 256 threads per batch row. 4 cols/thread.
// All fp32. Eigen solve via DEFLATION (largest eigenvector first, then a
// stable 2x2 solve in its orthogonal complement) — numerically robust against
// the lambda2 ~= lambda3 near-degeneracy that breaks the naive trig formula.
// ---------------------------------------------------------------------------

__global__ void __launch_bounds__(256, 4) lrf_kernel(
    const float* __restrict__ x0,
    const float* __restrict__ x0i,
    float* __restrict__ out)
{
    const int b = blockIdx.x;
    const int t = threadIdx.x;
    const int w = t >> 5;
    const int lane = t & 31;

    __shared__ float redf[8][9];   // per-warp partials: 6 cov + 3 sum
    __shared__ float redv[8][3];   // per-warp vi partials
    __shared__ float samp0[256];   // sampled deltas (gathered via g_inv)
    __shared__ float samp1[256];
    __shared__ float samp2[256];

    const float px = __ldg(&x0[3 * b + 0]);
    const float py = __ldg(&x0[3 * b + 1]);
    const float pz = __ldg(&x0[3 * b + 2]);

    const float* base = x0i + (size_t)b * 3072;
    const int c0 = t * 4;

    float4 u0 = *reinterpret_cast<const float4*>(base + c0);
    float4 u1 = *reinterpret_cast<const float4*>(base + 1024 + c0);
    float4 u2 = *reinterpret_cast<const float4*>(base + 2048 + c0);
    int4 inv4 = *reinterpret_cast<const int4*>(&g_inv[c0]);

    float X[4] = {u0.x - px, u0.y - px, u0.z - px, u0.w - px};
    float Y[4] = {u1.x - py, u1.y - py, u1.z - py, u1.w - py};
    float Z[4] = {u2.x - pz, u2.y - pz, u2.z - pz, u2.w - pz};
    int   iv[4] = {inv4.x, inv4.y, inv4.z, inv4.w};

#pragma unroll
    for (int k = 0; k < 4; k++) {
        int s = iv[k];
        if (s >= 0) {
            samp0[s] = X[k];
            samp1[s] = Y[k];
            samp2[s] = Z[k];
        }
    }

    // ----- phase 1: covariance (6) + column sum (3) -----
    float a00 = 0.f, a01 = 0.f, a02 = 0.f, a11 = 0.f, a12 = 0.f, a22 = 0.f;
    float s0 = 0.f, s1 = 0.f, s2 = 0.f;
#pragma unroll
    for (int k = 0; k < 4; k++) {
        float x = X[k], y = Y[k], z = Z[k];
        a00 = fmaf(x, x, a00); a01 = fmaf(x, y, a01); a02 = fmaf(x, z, a02);
        a11 = fmaf(y, y, a11); a12 = fmaf(y, z, a12); a22 = fmaf(z, z, a22);
        s0 += x; s1 += y; s2 += z;
    }
#pragma unroll
    for (int o = 16; o; o >>= 1) {
        a00 += __shfl_down_sync(0xffffffffu, a00, o);
        a01 += __shfl_down_sync(0xffffffffu, a01, o);
        a02 += __shfl_down_sync(0xffffffffu, a02, o);
        a11 += __shfl_down_sync(0xffffffffu, a11, o);
        a12 += __shfl_down_sync(0xffffffffu, a12, o);
        a22 += __shfl_down_sync(0xffffffffu, a22, o);
        s0  += __shfl_down_sync(0xffffffffu, s0, o);
        s1  += __shfl_down_sync(0xffffffffu, s1, o);
        s2  += __shfl_down_sync(0xffffffffu, s2, o);
    }
    if (lane == 0) {
        redf[w][0] = a00; redf[w][1] = a01; redf[w][2] = a02;
        redf[w][3] = a11; redf[w][4] = a12; redf[w][5] = a22;
        redf[w][6] = s0;  redf[w][7] = s1;  redf[w][8] = s2;
    }
    __syncthreads();   // B1

    float sj = 0.f;
    if (lane < 9) {
#pragma unroll
        for (int i = 0; i < 8; i++) sj += redf[i][lane];
    }
    const float invC = 1.0f / 1024.0f;
    const float M00 = __shfl_sync(0xffffffffu, sj, 0) * invC;
    const float M01 = __shfl_sync(0xffffffffu, sj, 1) * invC;
    const float M02 = __shfl_sync(0xffffffffu, sj, 2) * invC;
    const float M11 = __shfl_sync(0xffffffffu, sj, 3) * invC;
    const float M12 = __shfl_sync(0xffffffffu, sj, 4) * invC;
    const float M22 = __shfl_sync(0xffffffffu, sj, 5) * invC;
    const float S0  = __shfl_sync(0xffffffffu, sj, 6);
    const float S1  = __shfl_sync(0xffffffffu, sj, 7);
    const float S2  = __shfl_sync(0xffffffffu, sj, 8);

    // ----- phase 2: deflated fp32 eigen solve (redundant per thread) -----
    float zpx, zpy, zpz;
    {
        // (a) largest eigenvalue via trig formula (well-conditioned at r->1)
        float q = (M00 + M11 + M22) * (1.0f / 3.0f);
        float d00 = M00 - q, d11 = M11 - q, d22 = M22 - q;
        float p2 = d00 * d00 + d11 * d11 + d22 * d22
                 + 2.0f * (M01 * M01 + M02 * M02 + M12 * M12);
        float p = sqrtf(p2 * (1.0f / 6.0f));
        float zx, zy, zz;
        if (p < 1e-18f) {
            // isotropic: any direction; match "safe" fallback
            zx = 0.f; zy = 0.f; zz = 1.f;
        } else {
            float ip = 1.0f / p;
            float c00 = d00 * ip, c11 = d11 * ip, c22 = d22 * ip;
            float c01 = M01 * ip, c02 = M02 * ip, c12 = M12 * ip;
            float det = c00 * (c11 * c22 - c12 * c12)
                      - c01 * (c01 * c22 - c12 * c02)
                      + c02 * (c01 * c12 - c11 * c02);
            float r = fminf(1.0f, fmaxf(-1.0f, 0.5f * det));
            float phi = acosf(r) * (1.0f / 3.0f);
            float lmax = q + 2.0f * p * cosf(phi);

            // (b) eigenvector e1 of lmax via row cross-products (isolated -> stable)
            float m00 = M00 - lmax, m11 = M11 - lmax, m22 = M22 - lmax;
            float cx0 = M01 * M12 - M02 * m11;   // r0 x r1
            float cy0 = M02 * M01 - m00 * M12;
            float cz0 = m00 * m11 - M01 * M01;
            float cx1 = M01 * m22 - M02 * M12;   // r0 x r2
            float cy1 = M02 * M02 - m00 * m22;
            float cz1 = m00 * M12 - M01 * M02;
            float cx2 = m11 * m22 - M12 * M12;   // r1 x r2
            float cy2 = M12 * M02 - M01 * m22;
            float cz2 = M01 * M12 - m11 * M02;
            float n0 = cx0 * cx0 + cy0 * cy0 + cz0 * cz0;
            float n1 = cx1 * cx1 + cy1 * cy1 + cz1 * cz1;
            float n2 = cx2 * cx2 + cy2 * cy2 + cz2 * cz2;
            float ex, ey, ez, nn;
            if (n0 >= n1 && n0 >= n2)      { ex = cx0; ey = cy0; ez = cz0; nn = n0; }
            else if (n1 >= n2)             { ex = cx1; ey = cy1; ez = cz1; nn = n1; }
            else                           { ex = cx2; ey = cy2; ez = cz2; nn = n2; }
            if (nn < 1e-30f) { ex = 1.f; ey = 0.f; ez = 0.f; nn = 1.f; }
            float einv = rsqrtf(nn);
            ex *= einv; ey *= einv; ez *= einv;

            // (c) orthonormal basis {u,v} of complement of e1
            float uxx, uxy, uxz;
            float aex = fabsf(ex), aey = fabsf(ey), aez = fabsf(ez);
            if (aex <= aey && aex <= aez)      { uxx = 0.f; uxy = -ez; uxz =  ey; }  // x-axis cross e1
            else if (aey <= aez)               { uxx =  ez; uxy = 0.f; uxz = -ex; }  // y-axis cross e1
            else                               { uxx = -ey; uxy =  ex; uxz = 0.f; }  // z-axis cross e1
            float uinv = rsqrtf(uxx * uxx + uxy * uxy + uxz * uxz);
            uxx *= uinv; uxy *= uinv; uxz *= uinv;
            float vxx = ey * uxz - ez * uxy;
            float vxy = ez * uxx - ex * uxz;
            float vxz = ex * uxy - ey * uxx;

            // (d) 2x2 projected matrix B
            float Mux = fmaf(M00, uxx, fmaf(M01, uxy, M02 * uxz));
            float Muy = fmaf(M01, uxx, fmaf(M11, uxy, M12 * uxz));
            float Muz = fmaf(M02, uxx, fmaf(M12, uxy, M22 * uxz));
            float Mvx = fmaf(M00, vxx, fmaf(M01, vxy, M02 * vxz));
            float Mvy = fmaf(M01, vxx, fmaf(M11, vxy, M12 * vxz));
            float Mvz = fmaf(M02, vxx, fmaf(M12, vxy, M22 * vxz));
            float b00 = fmaf(uxx, Mux, fmaf(uxy, Muy, uxz * Muz));
            float b01 = fmaf(uxx, Mvx, fmaf(uxy, Mvy, uxz * Mvz));
            float b11 = fmaf(vxx, Mvx, fmaf(vxy, Mvy, vxz * Mvz));

            // (e) smallest eigenvector of B (cancellation-free branch)
            float half = 0.5f * (b00 - b11);
            float rt = sqrtf(fmaf(half, half, b01 * b01));
            float cc, ss;
            if (half >= 0.f) { cc = b01;       ss = -(half + rt); }
            else             { cc = rt - half; ss = -b01; }
            float cn2 = fmaf(cc, cc, ss * ss);
            if (cn2 < 1e-30f) { cc = 1.f; ss = 0.f; cn2 = 1.f; }
            float cninv = rsqrtf(cn2);
            cc *= cninv; ss *= cninv;

            zx = fmaf(cc, uxx, ss * vxx);
            zy = fmaf(cc, uxy, ss * vxy);
            zz = fmaf(cc, uxz, ss * vxz);
        }

        // sign: s_ref = z . sum(xp - xpi) = -(z . sum(xs))
        float sgn = (-(zx * S0 + zy * S1 + zz * S2) < 0.f) ? -1.f : 1.f;
        zpx = zx * sgn; zpy = zy * sgn; zpz = zz * sgn;
    }

    // ----- phase 3: vi_c accumulation (from registers) -----
    float v0 = 0.f, v1 = 0.f, v2 = 0.f;
#pragma unroll
    for (int k = 0; k < 4; k++) {
        float x = X[k], y = Y[k], z = Z[k];
        float nrm = fmaf(zpx, x, fmaf(zpy, y, zpz * z));
        float l2  = sqrtf(fmaf(x, x, fmaf(y, y, z * z)));
        float am  = 1.0f - l2;                 // R_LRF = 1
        float coef = (am * am) * (nrm * nrm);
        v0 = fmaf(coef, fmaf(-nrm, zpx, x), v0);
        v1 = fmaf(coef, fmaf(-nrm, zpy, y), v1);
        v2 = fmaf(coef, fmaf(-nrm, zpz, z), v2);
    }
#pragma unroll
    for (int o = 16; o; o >>= 1) {
        v0 += __shfl_down_sync(0xffffffffu, v0, o);
        v1 += __shfl_down_sync(0xffffffffu, v1, o);
        v2 += __shfl_down_sync(0xffffffffu, v2, o);
    }
    if (lane == 0) {
        redv[w][0] = v0; redv[w][1] = v1; redv[w][2] = v2;
    }
    __syncthreads();   // B2

    float c0f = 0.f, c1f = 0.f, c2f = 0.f;
#pragma unroll
    for (int i = 0; i < 8; i++) {
        c0f += redv[i][0]; c1f += redv[i][1]; c2f += redv[i][2];
    }
    float nrm2 = fmaf(c0f, c0f, fmaf(c1f, c1f, c2f * c2f));
    float invn = rsqrtf(nrm2);
    float ax = c0f * invn, ay = c1f * invn, az = c2f * invn;
    float yx = ay * zpz - az * zpy;
    float yy = az * zpx - ax * zpz;
    float yz = ax * zpy - ay * zpx;

    // ----- phase 4: project 256 sampled columns -----
    const float vx = samp0[t], vy = samp1[t], vz = samp2[t];
    const size_t ob = (size_t)b * 768 + t;
    out[ob]       = fmaf(ax, vx, fmaf(ay, vy, az * vz));
    out[ob + 256] = fmaf(yx, vx, fmaf(yy, vy, yz * vz));
    out[ob + 512] = fmaf(zpx, vx, fmaf(zpy, vy, zpz * vz));
}

// ---------------------------------------------------------------------------

extern "C" void kernel_launch(void* const* d_in, const int* in_sizes, int n_in,
                              void* d_out, int out_size) {
    const float* x0  = (const float*)d_in[0];
    const float* x0i = (const float*)d_in[1];
    if (n_in >= 2 && in_sizes[0] > in_sizes[1]) {
        const float* tmp = x0; x0 = x0i; x0i = tmp;
    }
    int B;
    if (in_sizes[0] <= in_sizes[1]) B = in_sizes[0] / 3;
    else                            B = in_sizes[1] / 3;

    float* out = (float*)d_out;

    perm_kernel<<<1, 1024>>>();
    lrf_kernel<<<B, 256>>>(x0, x0i, out);
}

// round 4
// speedup vs baseline: 6.1338x; 1.6526x over previous
#include <cuda_runtime.h>
#include <stdint.h>
#include <math.h>
#include <algorithm>

// ---------------------------------------------------------------------------
// Permutation jax.random.permutation(key(42), 1024)[:256] — computed on HOST
// (threefry2x32 partitionable + one stable ascending sort round), uploaded as
// an async H2D memcpy to a device symbol (graph-capturable, no allocs).
// g_inv[col] = sample slot (0..255) or -1.
// ---------------------------------------------------------------------------

__device__ int g_inv[1024];

static uint32_t h_rotl32(uint32_t x, int r) { return (x << r) | (x >> (32 - r)); }

static void h_threefry2x32(uint32_t k0, uint32_t k1, uint32_t c0, uint32_t c1,
                           uint32_t& o0, uint32_t& o1) {
    uint32_t ks2 = k0 ^ k1 ^ 0x1BD11BDAu;
    uint32_t x0 = c0 + k0;
    uint32_t x1 = c1 + k1;
#define TF_G(r0, r1, r2, r3)                          \
    x0 += x1; x1 = h_rotl32(x1, r0); x1 ^= x0;        \
    x0 += x1; x1 = h_rotl32(x1, r1); x1 ^= x0;        \
    x0 += x1; x1 = h_rotl32(x1, r2); x1 ^= x0;        \
    x0 += x1; x1 = h_rotl32(x1, r3); x1 ^= x0;
    TF_G(13, 15, 26, 6)   x0 += k1;  x1 += ks2 + 1u;
    TF_G(17, 29, 16, 24)  x0 += ks2; x1 += k0 + 2u;
    TF_G(13, 15, 26, 6)   x0 += k0;  x1 += k1 + 3u;
    TF_G(17, 29, 16, 24)  x0 += k1;  x1 += ks2 + 4u;
    TF_G(13, 15, 26, 6)   x0 += ks2; x1 += k0 + 5u;
#undef TF_G
    o0 = x0; o1 = x1;
}

static int h_inv[1024];   // persists across graph replays (host source of memcpy)

static void build_perm_host() {
    uint32_t sk0, sk1;
    h_threefry2x32(0u, 42u, 0u, 1u, sk0, sk1);
    static uint64_t keys[1024];
    for (uint32_t i = 0; i < 1024; i++) {
        uint32_t b0, b1;
        h_threefry2x32(sk0, sk1, 0u, i, b0, b1);
        uint32_t bits = b0 ^ b1;
        keys[i] = ((uint64_t)bits << 32) | (uint64_t)i;   // stable via idx tiebreak
    }
    std::sort(keys, keys + 1024);
    for (int i = 0; i < 1024; i++) h_inv[i] = -1;
    for (int p = 0; p < 256; p++) {
        int col = (int)(keys[p] & 0xFFFFFFFFull);
        h_inv[col] = p;
    }
}

// ---------------------------------------------------------------------------
// Main LRF kernel: one block of 128 threads per batch row. 8 cols/thread.
// All fp32. Deflated eigen solve (proven in R3) computed in warp 0 only.
// ---------------------------------------------------------------------------

__global__ void __launch_bounds__(128, 8) lrf_kernel(
    const float* __restrict__ x0,
    const float* __restrict__ x0i,
    float* __restrict__ out)
{
    const int b = blockIdx.x;
    const int t = threadIdx.x;
    const int w = t >> 5;
    const int lane = t & 31;

    __shared__ float redf[4][9];   // per-warp partials: 6 cov + 3 sum
    __shared__ float redv[4][3];   // per-warp vi partials
    __shared__ float sbc[3];       // zp broadcast
    __shared__ float samp0[256];   // sampled deltas (scattered via g_inv)
    __shared__ float samp1[256];
    __shared__ float samp2[256];

    const float px = __ldg(&x0[3 * b + 0]);
    const float py = __ldg(&x0[3 * b + 1]);
    const float pz = __ldg(&x0[3 * b + 2]);

    const float* base = x0i + (size_t)b * 3072;
    const int c0 = t * 8;

    float4 u0a = *reinterpret_cast<const float4*>(base + c0);
    float4 u0b = *reinterpret_cast<const float4*>(base + c0 + 4);
    float4 u1a = *reinterpret_cast<const float4*>(base + 1024 + c0);
    float4 u1b = *reinterpret_cast<const float4*>(base + 1024 + c0 + 4);
    float4 u2a = *reinterpret_cast<const float4*>(base + 2048 + c0);
    float4 u2b = *reinterpret_cast<const float4*>(base + 2048 + c0 + 4);
    int4 iva = *reinterpret_cast<const int4*>(&g_inv[c0]);
    int4 ivb = *reinterpret_cast<const int4*>(&g_inv[c0 + 4]);

    float X[8] = {u0a.x - px, u0a.y - px, u0a.z - px, u0a.w - px,
                  u0b.x - px, u0b.y - px, u0b.z - px, u0b.w - px};
    float Y[8] = {u1a.x - py, u1a.y - py, u1a.z - py, u1a.w - py,
                  u1b.x - py, u1b.y - py, u1b.z - py, u1b.w - py};
    float Z[8] = {u2a.x - pz, u2a.y - pz, u2a.z - pz, u2a.w - pz,
                  u2b.x - pz, u2b.y - pz, u2b.z - pz, u2b.w - pz};
    int iv[8] = {iva.x, iva.y, iva.z, iva.w, ivb.x, ivb.y, ivb.z, ivb.w};

#pragma unroll
    for (int k = 0; k < 8; k++) {
        int s = iv[k];
        if (s >= 0) {
            samp0[s] = X[k];
            samp1[s] = Y[k];
            samp2[s] = Z[k];
        }
    }

    // ----- phase 1: covariance (6) + column sum (3) -----
    float a00 = 0.f, a01 = 0.f, a02 = 0.f, a11 = 0.f, a12 = 0.f, a22 = 0.f;
    float s0 = 0.f, s1 = 0.f, s2 = 0.f;
#pragma unroll
    for (int k = 0; k < 8; k++) {
        float x = X[k], y = Y[k], z = Z[k];
        a00 = fmaf(x, x, a00); a01 = fmaf(x, y, a01); a02 = fmaf(x, z, a02);
        a11 = fmaf(y, y, a11); a12 = fmaf(y, z, a12); a22 = fmaf(z, z, a22);
        s0 += x; s1 += y; s2 += z;
    }
#pragma unroll
    for (int o = 16; o; o >>= 1) {
        a00 += __shfl_down_sync(0xffffffffu, a00, o);
        a01 += __shfl_down_sync(0xffffffffu, a01, o);
        a02 += __shfl_down_sync(0xffffffffu, a02, o);
        a11 += __shfl_down_sync(0xffffffffu, a11, o);
        a12 += __shfl_down_sync(0xffffffffu, a12, o);
        a22 += __shfl_down_sync(0xffffffffu, a22, o);
        s0  += __shfl_down_sync(0xffffffffu, s0, o);
        s1  += __shfl_down_sync(0xffffffffu, s1, o);
        s2  += __shfl_down_sync(0xffffffffu, s2, o);
    }
    if (lane == 0) {
        redf[w][0] = a00; redf[w][1] = a01; redf[w][2] = a02;
        redf[w][3] = a11; redf[w][4] = a12; redf[w][5] = a22;
        redf[w][6] = s0;  redf[w][7] = s1;  redf[w][8] = s2;
    }
    __syncthreads();   // B1

    // ----- phase 2: eigen solve in warp 0 only (deflation, fp32) -----
    if (w == 0) {
        float sj = 0.f;
        if (lane < 9) {
#pragma unroll
            for (int i = 0; i < 4; i++) sj += redf[i][lane];
        }
        const float invC = 1.0f / 1024.0f;
        const float M00 = __shfl_sync(0xffffffffu, sj, 0) * invC;
        const float M01 = __shfl_sync(0xffffffffu, sj, 1) * invC;
        const float M02 = __shfl_sync(0xffffffffu, sj, 2) * invC;
        const float M11 = __shfl_sync(0xffffffffu, sj, 3) * invC;
        const float M12 = __shfl_sync(0xffffffffu, sj, 4) * invC;
        const float M22 = __shfl_sync(0xffffffffu, sj, 5) * invC;
        const float S0  = __shfl_sync(0xffffffffu, sj, 6);
        const float S1  = __shfl_sync(0xffffffffu, sj, 7);
        const float S2  = __shfl_sync(0xffffffffu, sj, 8);

        // (a) largest eigenvalue via trig formula (well-conditioned at r->1)
        float q = (M00 + M11 + M22) * (1.0f / 3.0f);
        float d00 = M00 - q, d11 = M11 - q, d22 = M22 - q;
        float p2 = d00 * d00 + d11 * d11 + d22 * d22
                 + 2.0f * (M01 * M01 + M02 * M02 + M12 * M12);
        float p = sqrtf(p2 * (1.0f / 6.0f));
        float zx, zy, zz;
        if (p < 1e-18f) {
            zx = 0.f; zy = 0.f; zz = 1.f;
        } else {
            float ip = 1.0f / p;
            float c00 = d00 * ip, c11 = d11 * ip, c22 = d22 * ip;
            float c01 = M01 * ip, c02 = M02 * ip, c12 = M12 * ip;
            float det = c00 * (c11 * c22 - c12 * c12)
                      - c01 * (c01 * c22 - c12 * c02)
                      + c02 * (c01 * c12 - c11 * c02);
            float r = fminf(1.0f, fmaxf(-1.0f, 0.5f * det));
            float phi = acosf(r) * (1.0f / 3.0f);
            float lmax = q + 2.0f * p * cosf(phi);

            // (b) eigenvector e1 of lmax via row cross-products
            float m00 = M00 - lmax, m11 = M11 - lmax, m22 = M22 - lmax;
            float cx0 = M01 * M12 - M02 * m11;
            float cy0 = M02 * M01 - m00 * M12;
            float cz0 = m00 * m11 - M01 * M01;
            float cx1 = M01 * m22 - M02 * M12;
            float cy1 = M02 * M02 - m00 * m22;
            float cz1 = m00 * M12 - M01 * M02;
            float cx2 = m11 * m22 - M12 * M12;
            float cy2 = M12 * M02 - M01 * m22;
            float cz2 = M01 * M12 - m11 * M02;
            float n0 = cx0 * cx0 + cy0 * cy0 + cz0 * cz0;
            float n1 = cx1 * cx1 + cy1 * cy1 + cz1 * cz1;
            float n2 = cx2 * cx2 + cy2 * cy2 + cz2 * cz2;
            float ex, ey, ez, nn;
            if (n0 >= n1 && n0 >= n2)      { ex = cx0; ey = cy0; ez = cz0; nn = n0; }
            else if (n1 >= n2)             { ex = cx1; ey = cy1; ez = cz1; nn = n1; }
            else                           { ex = cx2; ey = cy2; ez = cz2; nn = n2; }
            if (nn < 1e-30f) { ex = 1.f; ey = 0.f; ez = 0.f; nn = 1.f; }
            float einv = rsqrtf(nn);
            ex *= einv; ey *= einv; ez *= einv;

            // (c) orthonormal basis {u,v} of complement of e1
            float uxx, uxy, uxz;
            float aex = fabsf(ex), aey = fabsf(ey), aez = fabsf(ez);
            if (aex <= aey && aex <= aez)      { uxx = 0.f; uxy = -ez; uxz =  ey; }
            else if (aey <= aez)               { uxx =  ez; uxy = 0.f; uxz = -ex; }
            else                               { uxx = -ey; uxy =  ex; uxz = 0.f; }
            float uinv = rsqrtf(uxx * uxx + uxy * uxy + uxz * uxz);
            uxx *= uinv; uxy *= uinv; uxz *= uinv;
            float vxx = ey * uxz - ez * uxy;
            float vxy = ez * uxx - ex * uxz;
            float vxz = ex * uxy - ey * uxx;

            // (d) 2x2 projected matrix B
            float Mux = fmaf(M00, uxx, fmaf(M01, uxy, M02 * uxz));
            float Muy = fmaf(M01, uxx, fmaf(M11, uxy, M12 * uxz));
            float Muz = fmaf(M02, uxx, fmaf(M12, uxy, M22 * uxz));
            float Mvx = fmaf(M00, vxx, fmaf(M01, vxy, M02 * vxz));
            float Mvy = fmaf(M01, vxx, fmaf(M11, vxy, M12 * vxz));
            float Mvz = fmaf(M02, vxx, fmaf(M12, vxy, M22 * vxz));
            float b00 = fmaf(uxx, Mux, fmaf(uxy, Muy, uxz * Muz));
            float b01 = fmaf(uxx, Mvx, fmaf(uxy, Mvy, uxz * Mvz));
            float b11 = fmaf(vxx, Mvx, fmaf(vxy, Mvy, vxz * Mvz));

            // (e) smallest eigenvector of B (cancellation-free)
            float half = 0.5f * (b00 - b11);
            float rt = sqrtf(fmaf(half, half, b01 * b01));
            float cc, ss;
            if (half >= 0.f) { cc = b01;       ss = -(half + rt); }
            else             { cc = rt - half; ss = -b01; }
            float cn2 = fmaf(cc, cc, ss * ss);
            if (cn2 < 1e-30f) { cc = 1.f; ss = 0.f; cn2 = 1.f; }
            float cninv = rsqrtf(cn2);
            cc *= cninv; ss *= cninv;

            zx = fmaf(cc, uxx, ss * vxx);
            zy = fmaf(cc, uxy, ss * vxy);
            zz = fmaf(cc, uxz, ss * vxz);
        }

        float sgn = (-(zx * S0 + zy * S1 + zz * S2) < 0.f) ? -1.f : 1.f;
        if (lane == 0) {
            sbc[0] = zx * sgn;
            sbc[1] = zy * sgn;
            sbc[2] = zz * sgn;
        }
    }
    __syncthreads();   // B2

    const float zpx = sbc[0], zpy = sbc[1], zpz = sbc[2];

    // ----- phase 3: vi_c accumulation (from registers) -----
    float v0 = 0.f, v1 = 0.f, v2 = 0.f;
#pragma unroll
    for (int k = 0; k < 8; k++) {
        float x = X[k], y = Y[k], z = Z[k];
        float nrm = fmaf(zpx, x, fmaf(zpy, y, zpz * z));
        float l2  = sqrtf(fmaf(x, x, fmaf(y, y, z * z)));
        float am  = 1.0f - l2;                 // R_LRF = 1
        float coef = (am * am) * (nrm * nrm);
        v0 = fmaf(coef, fmaf(-nrm, zpx, x), v0);
        v1 = fmaf(coef, fmaf(-nrm, zpy, y), v1);
        v2 = fmaf(coef, fmaf(-nrm, zpz, z), v2);
    }
#pragma unroll
    for (int o = 16; o; o >>= 1) {
        v0 += __shfl_down_sync(0xffffffffu, v0, o);
        v1 += __shfl_down_sync(0xffffffffu, v1, o);
        v2 += __shfl_down_sync(0xffffffffu, v2, o);
    }
    if (lane == 0) {
        redv[w][0] = v0; redv[w][1] = v1; redv[w][2] = v2;
    }
    __syncthreads();   // B3

    // redundant combine + frame (cheap: ~30 ops)
    float c0f = 0.f, c1f = 0.f, c2f = 0.f;
#pragma unroll
    for (int i = 0; i < 4; i++) {
        c0f += redv[i][0]; c1f += redv[i][1]; c2f += redv[i][2];
    }
    float nrm2 = fmaf(c0f, c0f, fmaf(c1f, c1f, c2f * c2f));
    float invn = rsqrtf(nrm2);
    float ax = c0f * invn, ay = c1f * invn, az = c2f * invn;
    float yx = ay * zpz - az * zpy;
    float yy = az * zpx - ax * zpz;
    float yz = ax * zpy - ay * zpx;

    // ----- phase 4: project 2 sampled columns per thread (float2 stores) -----
    const int s0i = 2 * t;
    const float vxa = samp0[s0i],     vya = samp1[s0i],     vza = samp2[s0i];
    const float vxb = samp0[s0i + 1], vyb = samp1[s0i + 1], vzb = samp2[s0i + 1];
    float* ob = out + (size_t)b * 768 + s0i;
    *reinterpret_cast<float2*>(ob) =
        make_float2(fmaf(ax, vxa, fmaf(ay, vya, az * vza)),
                    fmaf(ax, vxb, fmaf(ay, vyb, az * vzb)));
    *reinterpret_cast<float2*>(ob + 256) =
        make_float2(fmaf(yx, vxa, fmaf(yy, vya, yz * vza)),
                    fmaf(yx, vxb, fmaf(yy, vyb, yz * vzb)));
    *reinterpret_cast<float2*>(ob + 512) =
        make_float2(fmaf(zpx, vxa, fmaf(zpy, vya, zpz * vza)),
                    fmaf(zpx, vxb, fmaf(zpy, vyb, zpz * vzb)));
}

// ---------------------------------------------------------------------------

extern "C" void kernel_launch(void* const* d_in, const int* in_sizes, int n_in,
                              void* d_out, int out_size) {
    const float* x0  = (const float*)d_in[0];
    const float* x0i = (const float*)d_in[1];
    if (n_in >= 2 && in_sizes[0] > in_sizes[1]) {
        const float* tmp = x0; x0 = x0i; x0i = tmp;
    }
    int B;
    if (in_sizes[0] <= in_sizes[1]) B = in_sizes[0] / 3;
    else                            B = in_sizes[1] / 3;

    float* out = (float*)d_out;

    build_perm_host();  // deterministic; recomputed every call (stateless)
    cudaMemcpyToSymbolAsync(g_inv, h_inv, sizeof(h_inv), 0,
                            cudaMemcpyHostToDevice, 0);

    lrf_kernel<<<B, 128>>>(x0, x0i, out);
}